// round 2
// baseline (speedup 1.0000x reference)
#include <cuda_runtime.h>
#include <cuda_bf16.h>
#include <math.h>

#define N_NODES_MAX 100000
#define N_EDGES_MAX 1600000
#define FEAT0 128
#define FEAT1 64

// ---------------- scratch (allocation-free: __device__ globals) ----------------
__device__ int   g_is64;                      // 1 if edge arrays are int64, 0 if int32
__device__ int   g_erow32[N_EDGES_MAX];
__device__ int   g_ecol32[N_EDGES_MAX];
__device__ int   g_rowptr[N_NODES_MAX + 1];
__device__ float g_dinv[N_NODES_MAX];
__device__ float g_h0[(size_t)N_NODES_MAX * FEAT0];   // x@W0+b0
__device__ float g_s1[(size_t)N_NODES_MAX * FEAT0];   // relu(spmm(h0))
__device__ float g_h1[(size_t)N_NODES_MAX * FEAT1];   // s1@W1+b1

// ---------------- dtype detect: odd 32-bit words of sorted edge_row ----------------
// int64 case: words [0,m) are the first m/2 edges; odd words are high halves == 0.
// int32 case: odd words are row values spanning up to ~n-1 (nonzero near the end).
__global__ void detect_kernel(const unsigned int* __restrict__ raw, int m, int* is64) {
    __shared__ unsigned int s_nz;
    if (threadIdx.x == 0) s_nz = 0u;
    __syncthreads();
    unsigned int acc = 0u;
    for (int i = 1 + 2 * (int)threadIdx.x; i < m; i += 2 * (int)blockDim.x)
        acc |= raw[i];
    if (acc) atomicOr(&s_nz, 1u);
    __syncthreads();
    if (threadIdx.x == 0) *is64 = (s_nz == 0u) ? 1 : 0;
}

// ---------------- normalize both edge arrays to int32 ----------------
__global__ void convert_kernel(const void* __restrict__ erow, const void* __restrict__ ecol,
                               int m, int* __restrict__ erow32, int* __restrict__ ecol32) {
    int i = blockIdx.x * blockDim.x + threadIdx.x;
    if (i >= m) return;
    if (g_is64) {
        erow32[i] = (int)((const long long*)erow)[i];
        ecol32[i] = (int)((const long long*)ecol)[i];
    } else {
        erow32[i] = ((const int*)erow)[i];
        ecol32[i] = ((const int*)ecol)[i];
    }
}

// ---------------- rowptr via binary search (edge_row is sorted) ----------------
__global__ void build_rowptr_kernel(const int* __restrict__ erow, int m, int n,
                                    int* __restrict__ rowptr) {
    int i = blockIdx.x * blockDim.x + threadIdx.x;
    if (i > n) return;
    int lo = 0, hi = m;
    while (lo < hi) {
        int mid = (lo + hi) >> 1;
        if (erow[mid] < i) lo = mid + 1; else hi = mid;
    }
    rowptr[i] = lo;
}

__global__ void dinv_kernel(const int* __restrict__ rowptr, float* __restrict__ dinv, int n) {
    int i = blockIdx.x * blockDim.x + threadIdx.x;
    if (i >= n) return;
    int d = rowptr[i + 1] - rowptr[i];
    dinv[i] = (d > 0) ? rsqrtf((float)d) : 0.0f;
}

// ---------------- fp32 tiled GEMM: C[nrows,N] = A[nrows,128] * W[128,N] + bias ----------------
template <int N>
__global__ void gemm_bias_kernel(const float* __restrict__ A, const float* __restrict__ W,
                                 const float* __restrict__ bias, float* __restrict__ C,
                                 int nrows) {
    constexpr int BM = 64;
    constexpr int K = 128;
    constexpr int TM = 4;
    constexpr int TN = N / 16;
    constexpr int ASTR = K + 4;

    extern __shared__ float sm[];
    float* Ws = sm;            // K*N
    float* As = sm + K * N;    // BM*ASTR

    const int tid = threadIdx.x;
    const int row0 = blockIdx.x * BM;

    {
        const float4* W4 = (const float4*)W;
        float4* Ws4 = (float4*)Ws;
        #pragma unroll 4
        for (int idx = tid; idx < K * N / 4; idx += 256) Ws4[idx] = W4[idx];
    }
    {
        const float4* A4 = (const float4*)A;
        #pragma unroll 2
        for (int idx = tid; idx < BM * (K / 4); idx += 256) {
            int r  = idx / (K / 4);
            int c4 = idx % (K / 4);
            float4 v = make_float4(0.f, 0.f, 0.f, 0.f);
            if (row0 + r < nrows) v = A4[(size_t)(row0 + r) * (K / 4) + c4];
            *(float4*)&As[r * ASTR + c4 * 4] = v;
        }
    }
    __syncthreads();

    const int tx = tid & 15;
    const int ty = tid >> 4;

    float acc[TM][TN];
    #pragma unroll
    for (int i = 0; i < TM; i++)
        #pragma unroll
        for (int j = 0; j < TN; j++) acc[i][j] = 0.f;

    const float* Ap = &As[(ty * TM) * ASTR];
    #pragma unroll 4
    for (int k = 0; k < K; k++) {
        float a[TM];
        #pragma unroll
        for (int i = 0; i < TM; i++) a[i] = Ap[i * ASTR + k];
        float b[TN];
        #pragma unroll
        for (int j = 0; j < TN; j += 4) {
            float4 bv = *(const float4*)&Ws[k * N + tx * TN + j];
            b[j] = bv.x; b[j + 1] = bv.y; b[j + 2] = bv.z; b[j + 3] = bv.w;
        }
        #pragma unroll
        for (int i = 0; i < TM; i++)
            #pragma unroll
            for (int j = 0; j < TN; j++) acc[i][j] = fmaf(a[i], b[j], acc[i][j]);
    }

    float bb[TN];
    #pragma unroll
    for (int j = 0; j < TN; j += 4) {
        float4 bv = *(const float4*)&bias[tx * TN + j];
        bb[j] = bv.x; bb[j + 1] = bv.y; bb[j + 2] = bv.z; bb[j + 3] = bv.w;
    }
    #pragma unroll
    for (int i = 0; i < TM; i++) {
        int r = row0 + ty * TM + i;
        if (r >= nrows) break;
        #pragma unroll
        for (int j = 0; j < TN; j += 4) {
            float4 o;
            o.x = acc[i][j]     + bb[j];
            o.y = acc[i][j + 1] + bb[j + 1];
            o.z = acc[i][j + 2] + bb[j + 2];
            o.w = acc[i][j + 3] + bb[j + 3];
            *(float4*)&C[(size_t)r * N + tx * TN + j] = o;
        }
    }
}

// ---------------- SpMM width-128 + ReLU: warp per row, float4 per lane ----------------
__global__ void spmm_relu128_kernel(const int* __restrict__ ecol,
                                    const int* __restrict__ rowptr,
                                    const float* __restrict__ dinv,
                                    const float* __restrict__ Hin,
                                    float* __restrict__ Hout, int n) {
    int gw = (blockIdx.x * blockDim.x + threadIdx.x) >> 5;
    int lane = threadIdx.x & 31;
    if (gw >= n) return;
    int s = rowptr[gw], e = rowptr[gw + 1];
    float di = dinv[gw];
    const float4* H4 = (const float4*)Hin;
    float4 acc = make_float4(0.f, 0.f, 0.f, 0.f);
    for (int ei = s; ei < e; ei++) {
        int c = __ldg(&ecol[ei]);
        float v = di * __ldg(&dinv[c]);
        float4 h = __ldg(&H4[(size_t)c * 32 + lane]);
        acc.x = fmaf(v, h.x, acc.x);
        acc.y = fmaf(v, h.y, acc.y);
        acc.z = fmaf(v, h.z, acc.z);
        acc.w = fmaf(v, h.w, acc.w);
    }
    acc.x = fmaxf(acc.x, 0.f); acc.y = fmaxf(acc.y, 0.f);
    acc.z = fmaxf(acc.z, 0.f); acc.w = fmaxf(acc.w, 0.f);
    ((float4*)Hout)[(size_t)gw * 32 + lane] = acc;
}

// ---------------- SpMM width-64 + fused log_softmax -> d_out ----------------
__global__ void spmm_lsm64_kernel(const int* __restrict__ ecol,
                                  const int* __restrict__ rowptr,
                                  const float* __restrict__ dinv,
                                  const float* __restrict__ Hin,
                                  float* __restrict__ out, int n) {
    int gw = (blockIdx.x * blockDim.x + threadIdx.x) >> 5;
    int lane = threadIdx.x & 31;
    if (gw >= n) return;
    int s = rowptr[gw], e = rowptr[gw + 1];
    float di = dinv[gw];
    const float2* H2 = (const float2*)Hin;
    float2 acc = make_float2(0.f, 0.f);
    for (int ei = s; ei < e; ei++) {
        int c = __ldg(&ecol[ei]);
        float v = di * __ldg(&dinv[c]);
        float2 h = __ldg(&H2[(size_t)c * 32 + lane]);
        acc.x = fmaf(v, h.x, acc.x);
        acc.y = fmaf(v, h.y, acc.y);
    }
    float mx = fmaxf(acc.x, acc.y);
    #pragma unroll
    for (int o = 16; o > 0; o >>= 1) mx = fmaxf(mx, __shfl_xor_sync(0xffffffffu, mx, o));
    float sum = expf(acc.x - mx) + expf(acc.y - mx);
    #pragma unroll
    for (int o = 16; o > 0; o >>= 1) sum += __shfl_xor_sync(0xffffffffu, sum, o);
    float lse = mx + logf(sum);
    float2 o2 = make_float2(acc.x - lse, acc.y - lse);
    ((float2*)out)[(size_t)gw * 32 + lane] = o2;
}

// ---------------- launch ----------------
extern "C" void kernel_launch(void* const* d_in, const int* in_sizes, int n_in,
                              void* d_out, int out_size) {
    const float* x    = (const float*)d_in[0];
    const void*  erow = d_in[1];
    const void*  ecol = d_in[2];
    const float* W0   = (const float*)d_in[3];
    const float* b0   = (const float*)d_in[4];
    const float* W1   = (const float*)d_in[5];
    const float* b1   = (const float*)d_in[6];
    float* out = (float*)d_out;

    const int n = in_sizes[0] / FEAT0;   // 100000
    const int m = in_sizes[1];           // 1600000

    int*   is64p;  cudaGetSymbolAddress((void**)&is64p,  g_is64);
    int*   erow32; cudaGetSymbolAddress((void**)&erow32, g_erow32);
    int*   ecol32; cudaGetSymbolAddress((void**)&ecol32, g_ecol32);
    int*   rowptr; cudaGetSymbolAddress((void**)&rowptr, g_rowptr);
    float* dinv;   cudaGetSymbolAddress((void**)&dinv,   g_dinv);
    float* h0;     cudaGetSymbolAddress((void**)&h0,     g_h0);
    float* s1;     cudaGetSymbolAddress((void**)&s1,     g_s1);
    float* h1;     cudaGetSymbolAddress((void**)&h1,     g_h1);

    const int smem128 = FEAT0 * FEAT0 * 4 + 64 * (FEAT0 + 4) * 4;
    const int smem64  = FEAT0 * FEAT1 * 4 + 64 * (FEAT0 + 4) * 4;
    cudaFuncSetAttribute(gemm_bias_kernel<FEAT0>, cudaFuncAttributeMaxDynamicSharedMemorySize, smem128);
    cudaFuncSetAttribute(gemm_bias_kernel<FEAT1>, cudaFuncAttributeMaxDynamicSharedMemorySize, smem64);

    // 0) detect edge dtype + normalize to int32
    detect_kernel<<<1, 1024>>>((const unsigned int*)erow, m, is64p);
    convert_kernel<<<(m + 255) / 256, 256>>>(erow, ecol, m, erow32, ecol32);
    // 1) rowptr
    build_rowptr_kernel<<<(n + 1 + 255) / 256, 256>>>(erow32, m, n, rowptr);
    // 2) dinv
    dinv_kernel<<<(n + 255) / 256, 256>>>(rowptr, dinv, n);
    // 3) h0 = x@W0 + b0
    gemm_bias_kernel<FEAT0><<<(n + 63) / 64, 256, smem128>>>(x, W0, b0, h0, n);
    // 4) s1 = relu(spmm(h0))
    spmm_relu128_kernel<<<(n + 7) / 8, 256>>>(ecol32, rowptr, dinv, h0, s1, n);
    // 5) h1 = s1@W1 + b1
    gemm_bias_kernel<FEAT1><<<(n + 63) / 64, 256, smem64>>>(s1, W1, b1, h1, n);
    // 6) out = log_softmax(spmm(h1))
    spmm_lsm64_kernel<<<(n + 7) / 8, 256>>>(ecol32, rowptr, dinv, h1, out, n);
}

// round 4
// speedup vs baseline: 1.2503x; 1.2503x over previous
#include <cuda_runtime.h>
#include <cuda_bf16.h>
#include <math.h>
#include <stdint.h>

#define N_NODES_MAX 100000
#define N_EDGES_MAX 1600000
#define FEAT0 128
#define FEAT1 64

// ---------------- scratch (allocation-free: __device__ globals) ----------------
__device__ int            g_is64;
__device__ int            g_erow32[N_EDGES_MAX];
__device__ int            g_ecol32[N_EDGES_MAX];
__device__ float          g_eval [N_EDGES_MAX];
__device__ int            g_rowptr[N_NODES_MAX + 1];
__device__ float          g_dinv[N_NODES_MAX];
__device__ __nv_bfloat16  g_h0b[(size_t)N_NODES_MAX * FEAT0];
__device__ __nv_bfloat16  g_s1b[(size_t)N_NODES_MAX * FEAT0];
__device__ __nv_bfloat16  g_h1b[(size_t)N_NODES_MAX * FEAT1];

// ---------------- packed f32x2 helpers ----------------
__device__ __forceinline__ unsigned long long pack_dup(float a) {
    unsigned long long d;
    asm("mov.b64 %0, {%1, %1};" : "=l"(d) : "r"(__float_as_uint(a)));
    return d;
}
__device__ __forceinline__ unsigned long long fma_f32x2(unsigned long long a,
                                                        unsigned long long b,
                                                        unsigned long long c) {
    unsigned long long d;
    asm("fma.rn.f32x2 %0, %1, %2, %3;" : "=l"(d) : "l"(a), "l"(b), "l"(c));
    return d;
}
__device__ __forceinline__ float2 unpack2(unsigned long long v) {
    unsigned int lo, hi;
    asm("mov.b64 {%0, %1}, %2;" : "=r"(lo), "=r"(hi) : "l"(v));
    return make_float2(__uint_as_float(lo), __uint_as_float(hi));
}

// ============================ prep kernels ============================
__global__ void detect_kernel(const unsigned int* __restrict__ raw, int m, int* is64) {
    __shared__ unsigned int s_nz;
    if (threadIdx.x == 0) s_nz = 0u;
    __syncthreads();
    unsigned int acc = 0u;
    for (int i = 1 + 2 * (int)threadIdx.x; i < m; i += 2 * (int)blockDim.x) acc |= raw[i];
    if (acc) atomicOr(&s_nz, 1u);
    __syncthreads();
    if (threadIdx.x == 0) *is64 = (s_nz == 0u) ? 1 : 0;
}

__global__ void convert_kernel(const void* __restrict__ erow, const void* __restrict__ ecol,
                               int m, int* __restrict__ erow32, int* __restrict__ ecol32) {
    int i = blockIdx.x * blockDim.x + threadIdx.x;
    if (i >= m) return;
    if (g_is64) {
        erow32[i] = (int)((const long long*)erow)[i];
        ecol32[i] = (int)((const long long*)ecol)[i];
    } else {
        erow32[i] = ((const int*)erow)[i];
        ecol32[i] = ((const int*)ecol)[i];
    }
}

__global__ void build_rowptr_kernel(const int* __restrict__ erow, int m, int n,
                                    int* __restrict__ rowptr) {
    int i = blockIdx.x * blockDim.x + threadIdx.x;
    if (i > n) return;
    int lo = 0, hi = m;
    while (lo < hi) {
        int mid = (lo + hi) >> 1;
        if (erow[mid] < i) lo = mid + 1; else hi = mid;
    }
    rowptr[i] = lo;
}

__global__ void dinv_kernel(const int* __restrict__ rowptr, float* __restrict__ dinv, int n) {
    int i = blockIdx.x * blockDim.x + threadIdx.x;
    if (i >= n) return;
    int d = rowptr[i + 1] - rowptr[i];
    dinv[i] = (d > 0) ? rsqrtf((float)d) : 0.0f;
}

__global__ void eval_kernel(const int* __restrict__ erow, const int* __restrict__ ecol,
                            const float* __restrict__ dinv, float* __restrict__ eval, int m) {
    int i = blockIdx.x * blockDim.x + threadIdx.x;
    if (i >= m) return;
    eval[i] = dinv[erow[i]] * dinv[ecol[i]];
}

// ============================ f32x2 SIMT GEMM ============================
// C[nrows,N](bf16) = A[nrows,128] @ W[128,N](f32) + bias.
// BM=128 rows/CTA, 256 threads as 16(tx) x 16(ty), TM=8 rows, TN=N/16 cols.
template <int N, typename TA>
__global__ void __launch_bounds__(256, 1)
gemm_f32x2_kernel(const TA* __restrict__ A, const float* __restrict__ W,
                  const float* __restrict__ bias, __nv_bfloat16* __restrict__ C,
                  int nrows) {
    constexpr int BM = 128;
    constexpr int K = 128;
    constexpr int TM = 8;
    constexpr int TN = N / 16;
    constexpr int TP = TN / 2;      // f32x2 pairs per thread
    constexpr int ASTR = K + 4;

    extern __shared__ float sm[];
    float* Ws = sm;                 // [K][N]
    float* As = sm + K * N;         // [BM][ASTR]

    const int tid  = threadIdx.x;
    const int row0 = blockIdx.x * BM;

    // ---- load W [K,N] fp32 ----
    {
        const float4* W4 = (const float4*)W;
        float4* Ws4 = (float4*)Ws;
        #pragma unroll
        for (int idx = tid; idx < K * N / 4; idx += 256) Ws4[idx] = W4[idx];
    }
    // ---- load A tile [BM,K] -> fp32 smem (zero-pad OOB rows) ----
    if constexpr (sizeof(TA) == 4) {
        const float4* A4 = (const float4*)A;
        #pragma unroll
        for (int idx = tid; idx < BM * (K / 4); idx += 256) {
            int r  = idx / (K / 4);
            int c4 = idx % (K / 4);
            float4 v = make_float4(0.f, 0.f, 0.f, 0.f);
            if (row0 + r < nrows) v = A4[(size_t)(row0 + r) * (K / 4) + c4];
            *(float4*)&As[r * ASTR + c4 * 4] = v;
        }
    } else {
        const uint4* A8 = (const uint4*)A;   // 8 bf16 per uint4
        #pragma unroll
        for (int idx = tid; idx < BM * (K / 8); idx += 256) {
            int r  = idx / (K / 8);
            int c8 = idx % (K / 8);
            uint4 v = make_uint4(0, 0, 0, 0);
            if (row0 + r < nrows) v = A8[(size_t)(row0 + r) * (K / 8) + c8];
            float2 f0 = __bfloat1622float2(*(__nv_bfloat162*)&v.x);
            float2 f1 = __bfloat1622float2(*(__nv_bfloat162*)&v.y);
            float2 f2 = __bfloat1622float2(*(__nv_bfloat162*)&v.z);
            float2 f3 = __bfloat1622float2(*(__nv_bfloat162*)&v.w);
            float* dst = &As[r * ASTR + c8 * 8];
            *(float4*)(dst)     = make_float4(f0.x, f0.y, f1.x, f1.y);
            *(float4*)(dst + 4) = make_float4(f2.x, f2.y, f3.x, f3.y);
        }
    }
    __syncthreads();

    const int tx = tid & 15;
    const int ty = tid >> 4;

    unsigned long long acc[TM][TP];
    #pragma unroll
    for (int i = 0; i < TM; i++)
        #pragma unroll
        for (int p = 0; p < TP; p++) acc[i][p] = 0ull;

    const float* Ap = &As[(ty * TM) * ASTR];
    const float* Wp = &Ws[tx * TN];

    #pragma unroll 4
    for (int k = 0; k < K; k++) {
        unsigned long long av[TM];
        #pragma unroll
        for (int i = 0; i < TM; i++) av[i] = pack_dup(Ap[i * ASTR + k]);
        unsigned long long bp[TP];
        #pragma unroll
        for (int p = 0; p < TP; p += 2) {
            float4 bv = *(const float4*)&Wp[k * N + 2 * p];
            bp[p]     = pack_dup(0.f);  // placeholder; overwritten below
            asm("mov.b64 %0, {%1, %2};" : "=l"(bp[p])
                : "r"(__float_as_uint(bv.x)), "r"(__float_as_uint(bv.y)));
            asm("mov.b64 %0, {%1, %2};" : "=l"(bp[p + 1])
                : "r"(__float_as_uint(bv.z)), "r"(__float_as_uint(bv.w)));
        }
        #pragma unroll
        for (int i = 0; i < TM; i++)
            #pragma unroll
            for (int p = 0; p < TP; p++) acc[i][p] = fma_f32x2(av[i], bp[p], acc[i][p]);
    }

    // ---- epilogue: bias + bf16 store ----
    float bb[TN];
    #pragma unroll
    for (int j = 0; j < TN; j += 4) {
        float4 bv = __ldg((const float4*)&bias[tx * TN + j]);
        bb[j] = bv.x; bb[j + 1] = bv.y; bb[j + 2] = bv.z; bb[j + 3] = bv.w;
    }
    #pragma unroll
    for (int i = 0; i < TM; i++) {
        int r = row0 + ty * TM + i;
        if (r >= nrows) break;
        uint32_t o[TP];
        #pragma unroll
        for (int p = 0; p < TP; p++) {
            float2 f = unpack2(acc[i][p]);
            __nv_bfloat162 b2 = __floats2bfloat162_rn(f.x + bb[2 * p], f.y + bb[2 * p + 1]);
            o[p] = *(uint32_t*)&b2;
        }
        __nv_bfloat16* dst = &C[(size_t)r * N + tx * TN];
        if constexpr (TP == 4) *(uint4*)dst = make_uint4(o[0], o[1], o[2], o[3]);
        else                   *(uint2*)dst = make_uint2(o[0], o[1]);
    }
}

// ============================ SpMM kernels (bf16 features) ============================
__global__ void spmm_relu128_kernel(const int* __restrict__ ecol,
                                    const float* __restrict__ eval,
                                    const int* __restrict__ rowptr,
                                    const __nv_bfloat16* __restrict__ Hin,
                                    __nv_bfloat16* __restrict__ Hout, int n) {
    int gw = (blockIdx.x * blockDim.x + threadIdx.x) >> 5;
    int lane = threadIdx.x & 31;
    if (gw >= n) return;
    int s = rowptr[gw], e = rowptr[gw + 1];
    const uint2* H = (const uint2*)Hin;   // row = 32 uint2 (4 bf16 per lane)
    float4 acc = make_float4(0.f, 0.f, 0.f, 0.f);
    for (int ei = s; ei < e; ei++) {
        int c   = __ldg(&ecol[ei]);
        float v = __ldg(&eval[ei]);
        uint2 p = __ldg(&H[(size_t)c * 32 + lane]);
        float2 f0 = __bfloat1622float2(*(__nv_bfloat162*)&p.x);
        float2 f1 = __bfloat1622float2(*(__nv_bfloat162*)&p.y);
        acc.x = fmaf(v, f0.x, acc.x);
        acc.y = fmaf(v, f0.y, acc.y);
        acc.z = fmaf(v, f1.x, acc.z);
        acc.w = fmaf(v, f1.y, acc.w);
    }
    __nv_bfloat162 o0 = __floats2bfloat162_rn(fmaxf(acc.x, 0.f), fmaxf(acc.y, 0.f));
    __nv_bfloat162 o1 = __floats2bfloat162_rn(fmaxf(acc.z, 0.f), fmaxf(acc.w, 0.f));
    uint2 o; o.x = *(uint32_t*)&o0; o.y = *(uint32_t*)&o1;
    ((uint2*)Hout)[(size_t)gw * 32 + lane] = o;
}

__global__ void spmm_lsm64_kernel(const int* __restrict__ ecol,
                                  const float* __restrict__ eval,
                                  const int* __restrict__ rowptr,
                                  const __nv_bfloat16* __restrict__ Hin,
                                  float* __restrict__ out, int n) {
    int gw = (blockIdx.x * blockDim.x + threadIdx.x) >> 5;
    int lane = threadIdx.x & 31;
    if (gw >= n) return;
    int s = rowptr[gw], e = rowptr[gw + 1];
    const uint32_t* H = (const uint32_t*)Hin;  // row = 32 x (2 bf16)
    float2 acc = make_float2(0.f, 0.f);
    for (int ei = s; ei < e; ei++) {
        int c   = __ldg(&ecol[ei]);
        float v = __ldg(&eval[ei]);
        uint32_t p = __ldg(&H[(size_t)c * 32 + lane]);
        float2 f = __bfloat1622float2(*(__nv_bfloat162*)&p);
        acc.x = fmaf(v, f.x, acc.x);
        acc.y = fmaf(v, f.y, acc.y);
    }
    float mx = fmaxf(acc.x, acc.y);
    #pragma unroll
    for (int o = 16; o > 0; o >>= 1) mx = fmaxf(mx, __shfl_xor_sync(0xffffffffu, mx, o));
    float sum = expf(acc.x - mx) + expf(acc.y - mx);
    #pragma unroll
    for (int o = 16; o > 0; o >>= 1) sum += __shfl_xor_sync(0xffffffffu, sum, o);
    float lse = mx + logf(sum);
    ((float2*)out)[(size_t)gw * 32 + lane] = make_float2(acc.x - lse, acc.y - lse);
}

// ============================ launch ============================
extern "C" void kernel_launch(void* const* d_in, const int* in_sizes, int n_in,
                              void* d_out, int out_size) {
    const float* x    = (const float*)d_in[0];
    const void*  erow = d_in[1];
    const void*  ecol = d_in[2];
    const float* W0   = (const float*)d_in[3];
    const float* b0   = (const float*)d_in[4];
    const float* W1   = (const float*)d_in[5];
    const float* b1   = (const float*)d_in[6];
    float* out = (float*)d_out;

    const int n = in_sizes[0] / FEAT0;   // 100000
    const int m = in_sizes[1];           // 1600000

    int*   is64p;  cudaGetSymbolAddress((void**)&is64p,  g_is64);
    int*   erow32; cudaGetSymbolAddress((void**)&erow32, g_erow32);
    int*   ecol32; cudaGetSymbolAddress((void**)&ecol32, g_ecol32);
    float* evalp;  cudaGetSymbolAddress((void**)&evalp,  g_eval);
    int*   rowptr; cudaGetSymbolAddress((void**)&rowptr, g_rowptr);
    float* dinv;   cudaGetSymbolAddress((void**)&dinv,   g_dinv);
    __nv_bfloat16 *h0b, *s1b, *h1b;
    cudaGetSymbolAddress((void**)&h0b, g_h0b);
    cudaGetSymbolAddress((void**)&s1b, g_s1b);
    cudaGetSymbolAddress((void**)&h1b, g_h1b);

    const int smemG1 = (FEAT0 * FEAT0 + 128 * (FEAT0 + 4)) * 4;  // 133,120 B
    const int smemG2 = (FEAT0 * FEAT1 + 128 * (FEAT0 + 4)) * 4;  // 100,352 B
    cudaFuncSetAttribute((const void*)gemm_f32x2_kernel<FEAT0, float>,
                         cudaFuncAttributeMaxDynamicSharedMemorySize, smemG1);
    cudaFuncSetAttribute((const void*)gemm_f32x2_kernel<FEAT1, __nv_bfloat16>,
                         cudaFuncAttributeMaxDynamicSharedMemorySize, smemG2);

    const int ntiles = (n + 127) / 128;

    // prep
    detect_kernel<<<1, 1024>>>((const unsigned int*)erow, m, is64p);
    convert_kernel<<<(m + 255) / 256, 256>>>(erow, ecol, m, erow32, ecol32);
    build_rowptr_kernel<<<(n + 1 + 255) / 256, 256>>>(erow32, m, n, rowptr);
    dinv_kernel<<<(n + 255) / 256, 256>>>(rowptr, dinv, n);
    eval_kernel<<<(m + 255) / 256, 256>>>(erow32, ecol32, dinv, evalp, m);

    // layer 0: h0 = x@W0+b0 (fp32 in, bf16 out), s1 = relu(spmm(h0))
    gemm_f32x2_kernel<FEAT0, float><<<ntiles, 256, smemG1>>>(x, W0, b0, h0b, n);
    spmm_relu128_kernel<<<(n + 7) / 8, 256>>>(ecol32, evalp, rowptr, h0b, s1b, n);
    // layer 1: h1 = s1@W1+b1 (bf16 in, bf16 out), out = log_softmax(spmm(h1))
    gemm_f32x2_kernel<FEAT1, __nv_bfloat16><<<ntiles, 256, smemG2>>>(s1b, W1, b1, h1b, n);
    spmm_lsm64_kernel<<<(n + 7) / 8, 256>>>(ecol32, evalp, rowptr, h1b, out, n);
}

// round 5
// speedup vs baseline: 2.3451x; 1.8756x over previous
#include <cuda_runtime.h>
#include <cuda_bf16.h>
#include <math.h>
#include <stdint.h>

#define N_NODES_MAX 100000
#define N_EDGES_MAX 1600000
#define FEAT0 128
#define FEAT1 64

// ---------------- scratch (allocation-free: __device__ globals) ----------------
__device__ int            g_is64;
__device__ int            g_erow32[N_EDGES_MAX];
__device__ int            g_ecol32[N_EDGES_MAX];
__device__ float          g_eval [N_EDGES_MAX];
__device__ int            g_rowptr[N_NODES_MAX + 1];
__device__ float          g_dinv[N_NODES_MAX];
__device__ __nv_bfloat16  g_h0b[(size_t)N_NODES_MAX * FEAT0];
__device__ __nv_bfloat16  g_s1b[(size_t)N_NODES_MAX * FEAT0];
__device__ __nv_bfloat16  g_h1b[(size_t)N_NODES_MAX * FEAT1];
__device__ __nv_bfloat16  g_w0t[FEAT0 * FEAT0];   // W0^T [N=128][K=128] bf16
__device__ __nv_bfloat16  g_w1t[FEAT1 * FEAT0];   // W1^T [N=64][K=128]  bf16

// ============================ prep kernels ============================
// dtype detect on the LAST 1024 words of sorted edge_row:
// int32 -> those are the largest row ids (nonzero); int64 -> odd words are high halves (0).
__global__ void detect_kernel(const unsigned int* __restrict__ raw, int m) {
    __shared__ unsigned int s_nz;
    if (threadIdx.x == 0) s_nz = 0u;
    __syncthreads();
    unsigned int acc = 0u;
    int start = m - 1024;
    for (int w = start + (int)threadIdx.x; w < m; w += (int)blockDim.x)
        if (w & 1) acc |= raw[w];
    if (acc) atomicOr(&s_nz, 1u);
    __syncthreads();
    if (threadIdx.x == 0) g_is64 = (s_nz == 0u) ? 1 : 0;
}

__global__ void convert_kernel(const void* __restrict__ erow, const void* __restrict__ ecol,
                               int m, int* __restrict__ erow32, int* __restrict__ ecol32) {
    int i = blockIdx.x * blockDim.x + threadIdx.x;
    if (i >= m) return;
    if (g_is64) {
        erow32[i] = (int)((const long long*)erow)[i];
        ecol32[i] = (int)((const long long*)ecol)[i];
    } else {
        erow32[i] = ((const int*)erow)[i];
        ecol32[i] = ((const int*)ecol)[i];
    }
}

__global__ void build_rowptr_kernel(const int* __restrict__ erow, int m, int n,
                                    int* __restrict__ rowptr) {
    int i = blockIdx.x * blockDim.x + threadIdx.x;
    if (i > n) return;
    int lo = 0, hi = m;
    while (lo < hi) {
        int mid = (lo + hi) >> 1;
        if (erow[mid] < i) lo = mid + 1; else hi = mid;
    }
    rowptr[i] = lo;
}

__global__ void dinv_kernel(const int* __restrict__ rowptr, float* __restrict__ dinv, int n) {
    int i = blockIdx.x * blockDim.x + threadIdx.x;
    if (i >= n) return;
    int d = rowptr[i + 1] - rowptr[i];
    dinv[i] = (d > 0) ? rsqrtf((float)d) : 0.0f;
}

__global__ void eval_kernel(const int* __restrict__ erow, const int* __restrict__ ecol,
                            const float* __restrict__ dinv, float* __restrict__ eval, int m) {
    int i = blockIdx.x * blockDim.x + threadIdx.x;
    if (i >= m) return;
    eval[i] = dinv[erow[i]] * dinv[ecol[i]];
}

// transpose both weights to bf16 [N][K] in one launch
__global__ void prep_weights_kernel(const float* __restrict__ W0, const float* __restrict__ W1,
                                    __nv_bfloat16* __restrict__ w0t,
                                    __nv_bfloat16* __restrict__ w1t) {
    int i = blockIdx.x * blockDim.x + threadIdx.x;
    if (i < FEAT0 * FEAT0) {
        int k = i / FEAT0, n = i % FEAT0;
        w0t[n * FEAT0 + k] = __float2bfloat16(W0[i]);
    } else if (i < FEAT0 * FEAT0 + FEAT0 * FEAT1) {
        int j = i - FEAT0 * FEAT0;
        int k = j / FEAT1, n = j % FEAT1;
        w1t[n * FEAT0 + k] = __float2bfloat16(W1[j]);
    }
}

// ============================ HMMA (mma.sync) bf16 GEMM ============================
__device__ __forceinline__ void mma_bf16(float* d, const uint32_t* a, uint32_t b0, uint32_t b1) {
    asm volatile(
        "mma.sync.aligned.m16n8k16.row.col.f32.bf16.bf16.f32 "
        "{%0,%1,%2,%3}, {%4,%5,%6,%7}, {%8,%9}, {%0,%1,%2,%3};"
        : "+f"(d[0]), "+f"(d[1]), "+f"(d[2]), "+f"(d[3])
        : "r"(a[0]), "r"(a[1]), "r"(a[2]), "r"(a[3]), "r"(b0), "r"(b1));
}

// C[nrows,N](bf16) = A[nrows,128] @ Wt^T + bias.  Wt: [N][128] bf16 (pre-transposed).
// 256 thr = 8 warps as 4(row) x 2(col). Warp tile: 32 rows x N/2 cols. K=128 in 8 steps.
template <int N, typename TA>
__global__ void __launch_bounds__(256)
gemm_mma_kernel(const TA* __restrict__ A, const __nv_bfloat16* __restrict__ Wt,
                const float* __restrict__ bias, __nv_bfloat16* __restrict__ C, int nrows) {
    constexpr int K = 128, BM = 128;
    constexpr int SA = 136;               // bf16 elems per smem row (272B: conflict-free frags)
    constexpr int NT = N / 2;             // warp col span
    constexpr int NTILES = NT / 8;

    extern __shared__ __nv_bfloat16 sm[];
    __nv_bfloat16* As = sm;               // [BM][SA]
    __nv_bfloat16* Bs = sm + BM * SA;     // [N][SA]

    const int tid  = threadIdx.x;
    const int wid  = tid >> 5;
    const int lane = tid & 31;
    const int wr   = wid >> 1;            // 0..3
    const int wc   = wid & 1;             // 0..1
    const int gID  = lane >> 2;           // 0..7
    const int tig  = lane & 3;            // 0..3
    const int row0 = blockIdx.x * BM;

    // ---- stage A (convert fp32 -> bf16 if needed) ----
    if constexpr (sizeof(TA) == 4) {
        const float4* A4 = (const float4*)A;
        #pragma unroll
        for (int idx = tid; idx < BM * (K / 4); idx += 256) {
            int r = idx >> 5, c4 = idx & 31;
            float4 v = make_float4(0.f, 0.f, 0.f, 0.f);
            if (row0 + r < nrows) v = A4[(size_t)(row0 + r) * 32 + c4];
            __nv_bfloat162 lo = __floats2bfloat162_rn(v.x, v.y);
            __nv_bfloat162 hi = __floats2bfloat162_rn(v.z, v.w);
            uint2 o; o.x = *(uint32_t*)&lo; o.y = *(uint32_t*)&hi;
            *(uint2*)&As[r * SA + c4 * 4] = o;
        }
    } else {
        const uint4* A8 = (const uint4*)A;
        #pragma unroll
        for (int idx = tid; idx < BM * (K / 8); idx += 256) {
            int r = idx >> 4, c8 = idx & 15;
            uint4 v = make_uint4(0, 0, 0, 0);
            if (row0 + r < nrows) v = A8[(size_t)(row0 + r) * 16 + c8];
            *(uint4*)&As[r * SA + c8 * 8] = v;
        }
    }
    // ---- stage Wt [N][128] bf16 ----
    {
        const uint4* B8 = (const uint4*)Wt;
        #pragma unroll
        for (int idx = tid; idx < N * (K / 8); idx += 256) {
            int r = idx >> 4, c8 = idx & 15;
            *(uint4*)&Bs[r * SA + c8 * 8] = B8[(size_t)r * 16 + c8];
        }
    }
    __syncthreads();

    float acc[2][NTILES][4];
    #pragma unroll
    for (int mt = 0; mt < 2; mt++)
        #pragma unroll
        for (int nt = 0; nt < NTILES; nt++)
            #pragma unroll
            for (int c = 0; c < 4; c++) acc[mt][nt][c] = 0.f;

    #pragma unroll
    for (int ks = 0; ks < 8; ks++) {
        const int k0 = ks * 16;
        uint32_t a[2][4];
        #pragma unroll
        for (int mt = 0; mt < 2; mt++) {
            const __nv_bfloat16* base = &As[(wr * 32 + mt * 16 + gID) * SA + k0 + 2 * tig];
            a[mt][0] = *(const uint32_t*)(base);
            a[mt][1] = *(const uint32_t*)(base + 8 * SA);
            a[mt][2] = *(const uint32_t*)(base + 8);
            a[mt][3] = *(const uint32_t*)(base + 8 * SA + 8);
        }
        #pragma unroll
        for (int nt = 0; nt < NTILES; nt++) {
            const __nv_bfloat16* bb = &Bs[(wc * NT + nt * 8 + gID) * SA + k0 + 2 * tig];
            uint32_t b0 = *(const uint32_t*)(bb);
            uint32_t b1 = *(const uint32_t*)(bb + 8);
            #pragma unroll
            for (int mt = 0; mt < 2; mt++) mma_bf16(acc[mt][nt], a[mt], b0, b1);
        }
    }

    // ---- epilogue: bias + bf16 store ----
    #pragma unroll
    for (int mt = 0; mt < 2; mt++) {
        const int r_a = row0 + wr * 32 + mt * 16 + gID;
        #pragma unroll
        for (int nt = 0; nt < NTILES; nt++) {
            const int col = wc * NT + nt * 8 + 2 * tig;
            float2 bv = __ldg((const float2*)&bias[col]);
            if (r_a < nrows) {
                __nv_bfloat162 o = __floats2bfloat162_rn(acc[mt][nt][0] + bv.x,
                                                         acc[mt][nt][1] + bv.y);
                *(uint32_t*)&C[(size_t)r_a * N + col] = *(uint32_t*)&o;
            }
            if (r_a + 8 < nrows) {
                __nv_bfloat162 o = __floats2bfloat162_rn(acc[mt][nt][2] + bv.x,
                                                         acc[mt][nt][3] + bv.y);
                *(uint32_t*)&C[(size_t)(r_a + 8) * N + col] = *(uint32_t*)&o;
            }
        }
    }
}

// ============================ SpMM kernels (bf16 features) ============================
__global__ void spmm_relu128_kernel(const int* __restrict__ ecol,
                                    const float* __restrict__ eval,
                                    const int* __restrict__ rowptr,
                                    const __nv_bfloat16* __restrict__ Hin,
                                    __nv_bfloat16* __restrict__ Hout, int n) {
    int gw = (blockIdx.x * blockDim.x + threadIdx.x) >> 5;
    int lane = threadIdx.x & 31;
    if (gw >= n) return;
    int s = rowptr[gw], e = rowptr[gw + 1];
    const uint2* H = (const uint2*)Hin;   // row = 32 uint2 (4 bf16/lane)
    float4 acc = make_float4(0.f, 0.f, 0.f, 0.f);
    for (int ei = s; ei < e; ei++) {
        int c   = __ldg(&ecol[ei]);
        float v = __ldg(&eval[ei]);
        uint2 p = __ldg(&H[(size_t)c * 32 + lane]);
        float2 f0 = __bfloat1622float2(*(__nv_bfloat162*)&p.x);
        float2 f1 = __bfloat1622float2(*(__nv_bfloat162*)&p.y);
        acc.x = fmaf(v, f0.x, acc.x);
        acc.y = fmaf(v, f0.y, acc.y);
        acc.z = fmaf(v, f1.x, acc.z);
        acc.w = fmaf(v, f1.y, acc.w);
    }
    __nv_bfloat162 o0 = __floats2bfloat162_rn(fmaxf(acc.x, 0.f), fmaxf(acc.y, 0.f));
    __nv_bfloat162 o1 = __floats2bfloat162_rn(fmaxf(acc.z, 0.f), fmaxf(acc.w, 0.f));
    uint2 o; o.x = *(uint32_t*)&o0; o.y = *(uint32_t*)&o1;
    ((uint2*)Hout)[(size_t)gw * 32 + lane] = o;
}

__global__ void spmm_lsm64_kernel(const int* __restrict__ ecol,
                                  const float* __restrict__ eval,
                                  const int* __restrict__ rowptr,
                                  const __nv_bfloat16* __restrict__ Hin,
                                  float* __restrict__ out, int n) {
    int gw = (blockIdx.x * blockDim.x + threadIdx.x) >> 5;
    int lane = threadIdx.x & 31;
    if (gw >= n) return;
    int s = rowptr[gw], e = rowptr[gw + 1];
    const uint32_t* H = (const uint32_t*)Hin;  // row = 32 x (2 bf16)
    float2 acc = make_float2(0.f, 0.f);
    for (int ei = s; ei < e; ei++) {
        int c   = __ldg(&ecol[ei]);
        float v = __ldg(&eval[ei]);
        uint32_t p = __ldg(&H[(size_t)c * 32 + lane]);
        float2 f = __bfloat1622float2(*(__nv_bfloat162*)&p);
        acc.x = fmaf(v, f.x, acc.x);
        acc.y = fmaf(v, f.y, acc.y);
    }
    float mx = fmaxf(acc.x, acc.y);
    #pragma unroll
    for (int o = 16; o > 0; o >>= 1) mx = fmaxf(mx, __shfl_xor_sync(0xffffffffu, mx, o));
    float sum = expf(acc.x - mx) + expf(acc.y - mx);
    #pragma unroll
    for (int o = 16; o > 0; o >>= 1) sum += __shfl_xor_sync(0xffffffffu, sum, o);
    float lse = mx + logf(sum);
    ((float2*)out)[(size_t)gw * 32 + lane] = make_float2(acc.x - lse, acc.y - lse);
}

// ============================ launch ============================
extern "C" void kernel_launch(void* const* d_in, const int* in_sizes, int n_in,
                              void* d_out, int out_size) {
    const float* x    = (const float*)d_in[0];
    const void*  erow = d_in[1];
    const void*  ecol = d_in[2];
    const float* W0   = (const float*)d_in[3];
    const float* b0   = (const float*)d_in[4];
    const float* W1   = (const float*)d_in[5];
    const float* b1   = (const float*)d_in[6];
    float* out = (float*)d_out;

    const int n = in_sizes[0] / FEAT0;   // 100000
    const int m = in_sizes[1];           // 1600000

    int*   erow32; cudaGetSymbolAddress((void**)&erow32, g_erow32);
    int*   ecol32; cudaGetSymbolAddress((void**)&ecol32, g_ecol32);
    float* evalp;  cudaGetSymbolAddress((void**)&evalp,  g_eval);
    int*   rowptr; cudaGetSymbolAddress((void**)&rowptr, g_rowptr);
    float* dinv;   cudaGetSymbolAddress((void**)&dinv,   g_dinv);
    __nv_bfloat16 *h0b, *s1b, *h1b, *w0t, *w1t;
    cudaGetSymbolAddress((void**)&h0b, g_h0b);
    cudaGetSymbolAddress((void**)&s1b, g_s1b);
    cudaGetSymbolAddress((void**)&h1b, g_h1b);
    cudaGetSymbolAddress((void**)&w0t, g_w0t);
    cudaGetSymbolAddress((void**)&w1t, g_w1t);

    const int smemG1 = (128 + FEAT0) * 136 * 2;  // 69,632 B
    const int smemG2 = (128 + FEAT1) * 136 * 2;  // 52,224 B
    cudaFuncSetAttribute((const void*)gemm_mma_kernel<FEAT0, float>,
                         cudaFuncAttributeMaxDynamicSharedMemorySize, smemG1);
    cudaFuncSetAttribute((const void*)gemm_mma_kernel<FEAT1, __nv_bfloat16>,
                         cudaFuncAttributeMaxDynamicSharedMemorySize, smemG2);

    const int ntiles = (n + 127) / 128;

    // prep
    detect_kernel<<<1, 256>>>((const unsigned int*)erow, m);
    convert_kernel<<<(m + 255) / 256, 256>>>(erow, ecol, m, erow32, ecol32);
    prep_weights_kernel<<<(FEAT0 * FEAT0 + FEAT0 * FEAT1 + 255) / 256, 256>>>(W0, W1, w0t, w1t);
    build_rowptr_kernel<<<(n + 1 + 255) / 256, 256>>>(erow32, m, n, rowptr);
    dinv_kernel<<<(n + 255) / 256, 256>>>(rowptr, dinv, n);
    eval_kernel<<<(m + 255) / 256, 256>>>(erow32, ecol32, dinv, evalp, m);

    // layer 0
    gemm_mma_kernel<FEAT0, float><<<ntiles, 256, smemG1>>>(x, w0t, b0, h0b, n);
    spmm_relu128_kernel<<<(n + 7) / 8, 256>>>(ecol32, evalp, rowptr, h0b, s1b, n);
    // layer 1
    gemm_mma_kernel<FEAT1, __nv_bfloat16><<<ntiles, 256, smemG2>>>(s1b, w1t, b1, h1b, n);
    spmm_lsm64_kernel<<<(n + 7) / 8, 256>>>(ecol32, evalp, rowptr, h1b, out, n);
}

// round 6
// speedup vs baseline: 2.4764x; 1.0560x over previous
#include <cuda_runtime.h>
#include <cuda_bf16.h>
#include <math.h>
#include <stdint.h>

#define N_NODES_MAX 100000
#define N_EDGES_MAX 1600000
#define FEAT0 128
#define FEAT1 64

// ---------------- scratch (allocation-free: __device__ globals) ----------------
__device__ int            g_is64;
__device__ int            g_erow32[N_EDGES_MAX];
__device__ int            g_ecol32[N_EDGES_MAX];
__device__ float          g_eval [N_EDGES_MAX];
__device__ int            g_rowptr[N_NODES_MAX + 1];
__device__ float          g_dinv[N_NODES_MAX];
__device__ __nv_bfloat16  g_h0b[(size_t)N_NODES_MAX * FEAT0];
__device__ __nv_bfloat16  g_s1b[(size_t)N_NODES_MAX * FEAT0];
__device__ __nv_bfloat16  g_h1b[(size_t)N_NODES_MAX * FEAT1];
__device__ __nv_bfloat16  g_w0t[FEAT0 * FEAT0];   // W0^T [N=128][K=128] bf16
__device__ __nv_bfloat16  g_w1t[FEAT1 * FEAT0];   // W1^T [N=64][K=128]  bf16

// ============================ prep kernels ============================
// dtype detect on the LAST 1024 words of sorted edge_row (int64 -> odd words are 0 high halves).
__global__ void detect_kernel(const unsigned int* __restrict__ raw, int m) {
    __shared__ unsigned int s_nz;
    if (threadIdx.x == 0) s_nz = 0u;
    __syncthreads();
    unsigned int acc = 0u;
    int start = m - 1024;
    for (int w = start + (int)threadIdx.x; w < m; w += (int)blockDim.x)
        if (w & 1) acc |= raw[w];
    if (acc) atomicOr(&s_nz, 1u);
    __syncthreads();
    if (threadIdx.x == 0) g_is64 = (s_nz == 0u) ? 1 : 0;
}

__device__ __forceinline__ int load_edge(const void* p, int i, int is64) {
    return is64 ? (int)((const long long*)p)[i] : ((const int*)p)[i];
}

// convert int64/int32 -> int32 AND build rowptr by boundary detection (erow sorted).
__global__ void convert_rowptr_kernel(const void* __restrict__ erow,
                                      const void* __restrict__ ecol,
                                      int m, int n,
                                      int* __restrict__ erow32, int* __restrict__ ecol32,
                                      int* __restrict__ rowptr) {
    int i = blockIdx.x * blockDim.x + threadIdx.x;
    if (i >= m) return;
    const int is64 = g_is64;
    int cur  = load_edge(erow, i, is64);
    int prev = (i > 0) ? load_edge(erow, i - 1, is64) : -1;
    erow32[i] = cur;
    ecol32[i] = load_edge(ecol, i, is64);
    for (int r = prev + 1; r <= cur; r++) rowptr[r] = i;
    if (i == m - 1)
        for (int r = cur + 1; r <= n; r++) rowptr[r] = m;
}

// dinv for n nodes + both weight transposes (bf16), one launch
__global__ void dinv_weights_kernel(const int* __restrict__ rowptr, float* __restrict__ dinv,
                                    int n, const float* __restrict__ W0,
                                    const float* __restrict__ W1,
                                    __nv_bfloat16* __restrict__ w0t,
                                    __nv_bfloat16* __restrict__ w1t) {
    int i = blockIdx.x * blockDim.x + threadIdx.x;
    if (i < n) {
        int d = rowptr[i + 1] - rowptr[i];
        dinv[i] = (d > 0) ? rsqrtf((float)d) : 0.0f;
        return;
    }
    int j = i - n;
    if (j < FEAT0 * FEAT0) {
        int k = j / FEAT0, c = j % FEAT0;
        w0t[c * FEAT0 + k] = __float2bfloat16(W0[j]);
    } else if (j < FEAT0 * FEAT0 + FEAT0 * FEAT1) {
        int q = j - FEAT0 * FEAT0;
        int k = q / FEAT1, c = q % FEAT1;
        w1t[c * FEAT0 + k] = __float2bfloat16(W1[q]);
    }
}

__global__ void eval_kernel(const int* __restrict__ erow, const int* __restrict__ ecol,
                            const float* __restrict__ dinv, float* __restrict__ eval, int m) {
    int i = blockIdx.x * blockDim.x + threadIdx.x;
    if (i >= m) return;
    eval[i] = dinv[erow[i]] * dinv[ecol[i]];
}

// ============================ HMMA (mma.sync) bf16 GEMM ============================
__device__ __forceinline__ void mma_bf16(float* d, const uint32_t* a, uint32_t b0, uint32_t b1) {
    asm volatile(
        "mma.sync.aligned.m16n8k16.row.col.f32.bf16.bf16.f32 "
        "{%0,%1,%2,%3}, {%4,%5,%6,%7}, {%8,%9}, {%0,%1,%2,%3};"
        : "+f"(d[0]), "+f"(d[1]), "+f"(d[2]), "+f"(d[3])
        : "r"(a[0]), "r"(a[1]), "r"(a[2]), "r"(a[3]), "r"(b0), "r"(b1));
}

template <int N, typename TA>
__global__ void __launch_bounds__(256)
gemm_mma_kernel(const TA* __restrict__ A, const __nv_bfloat16* __restrict__ Wt,
                const float* __restrict__ bias, __nv_bfloat16* __restrict__ C, int nrows) {
    constexpr int K = 128, BM = 128;
    constexpr int SA = 136;
    constexpr int NT = N / 2;
    constexpr int NTILES = NT / 8;

    extern __shared__ __nv_bfloat16 sm[];
    __nv_bfloat16* As = sm;               // [BM][SA]
    __nv_bfloat16* Bs = sm + BM * SA;     // [N][SA]

    const int tid  = threadIdx.x;
    const int wid  = tid >> 5;
    const int lane = tid & 31;
    const int wr   = wid >> 1;
    const int wc   = wid & 1;
    const int gID  = lane >> 2;
    const int tig  = lane & 3;
    const int row0 = blockIdx.x * BM;

    if constexpr (sizeof(TA) == 4) {
        const float4* A4 = (const float4*)A;
        #pragma unroll
        for (int idx = tid; idx < BM * (K / 4); idx += 256) {
            int r = idx >> 5, c4 = idx & 31;
            float4 v = make_float4(0.f, 0.f, 0.f, 0.f);
            if (row0 + r < nrows) v = A4[(size_t)(row0 + r) * 32 + c4];
            __nv_bfloat162 lo = __floats2bfloat162_rn(v.x, v.y);
            __nv_bfloat162 hi = __floats2bfloat162_rn(v.z, v.w);
            uint2 o; o.x = *(uint32_t*)&lo; o.y = *(uint32_t*)&hi;
            *(uint2*)&As[r * SA + c4 * 4] = o;
        }
    } else {
        const uint4* A8 = (const uint4*)A;
        #pragma unroll
        for (int idx = tid; idx < BM * (K / 8); idx += 256) {
            int r = idx >> 4, c8 = idx & 15;
            uint4 v = make_uint4(0, 0, 0, 0);
            if (row0 + r < nrows) v = A8[(size_t)(row0 + r) * 16 + c8];
            *(uint4*)&As[r * SA + c8 * 8] = v;
        }
    }
    {
        const uint4* B8 = (const uint4*)Wt;
        #pragma unroll
        for (int idx = tid; idx < N * (K / 8); idx += 256) {
            int r = idx >> 4, c8 = idx & 15;
            *(uint4*)&Bs[r * SA + c8 * 8] = B8[(size_t)r * 16 + c8];
        }
    }
    __syncthreads();

    float acc[2][NTILES][4];
    #pragma unroll
    for (int mt = 0; mt < 2; mt++)
        #pragma unroll
        for (int nt = 0; nt < NTILES; nt++)
            #pragma unroll
            for (int c = 0; c < 4; c++) acc[mt][nt][c] = 0.f;

    #pragma unroll
    for (int ks = 0; ks < 8; ks++) {
        const int k0 = ks * 16;
        uint32_t a[2][4];
        #pragma unroll
        for (int mt = 0; mt < 2; mt++) {
            const __nv_bfloat16* base = &As[(wr * 32 + mt * 16 + gID) * SA + k0 + 2 * tig];
            a[mt][0] = *(const uint32_t*)(base);
            a[mt][1] = *(const uint32_t*)(base + 8 * SA);
            a[mt][2] = *(const uint32_t*)(base + 8);
            a[mt][3] = *(const uint32_t*)(base + 8 * SA + 8);
        }
        #pragma unroll
        for (int nt = 0; nt < NTILES; nt++) {
            const __nv_bfloat16* bb = &Bs[(wc * NT + nt * 8 + gID) * SA + k0 + 2 * tig];
            uint32_t b0 = *(const uint32_t*)(bb);
            uint32_t b1 = *(const uint32_t*)(bb + 8);
            #pragma unroll
            for (int mt = 0; mt < 2; mt++) mma_bf16(acc[mt][nt], a[mt], b0, b1);
        }
    }

    #pragma unroll
    for (int mt = 0; mt < 2; mt++) {
        const int r_a = row0 + wr * 32 + mt * 16 + gID;
        #pragma unroll
        for (int nt = 0; nt < NTILES; nt++) {
            const int col = wc * NT + nt * 8 + 2 * tig;
            float2 bv = __ldg((const float2*)&bias[col]);
            if (r_a < nrows) {
                __nv_bfloat162 o = __floats2bfloat162_rn(acc[mt][nt][0] + bv.x,
                                                         acc[mt][nt][1] + bv.y);
                *(uint32_t*)&C[(size_t)r_a * N + col] = *(uint32_t*)&o;
            }
            if (r_a + 8 < nrows) {
                __nv_bfloat162 o = __floats2bfloat162_rn(acc[mt][nt][2] + bv.x,
                                                         acc[mt][nt][3] + bv.y);
                *(uint32_t*)&C[(size_t)(r_a + 8) * N + col] = *(uint32_t*)&o;
            }
        }
    }
}

// ============================ SpMM kernels (bf16 features, MLP-4 unroll) ============================
__global__ void spmm_relu128_kernel(const int* __restrict__ ecol,
                                    const float* __restrict__ eval,
                                    const int* __restrict__ rowptr,
                                    const __nv_bfloat16* __restrict__ Hin,
                                    __nv_bfloat16* __restrict__ Hout, int n) {
    int gw = (blockIdx.x * blockDim.x + threadIdx.x) >> 5;
    int lane = threadIdx.x & 31;
    if (gw >= n) return;
    int s = rowptr[gw], e = rowptr[gw + 1];
    const uint2* H = (const uint2*)Hin;   // row = 32 uint2 (4 bf16/lane)
    float4 acc = make_float4(0.f, 0.f, 0.f, 0.f);
    int ei = s;
    for (; ei + 4 <= e; ei += 4) {
        int   c0 = __ldg(&ecol[ei]),     c1 = __ldg(&ecol[ei + 1]);
        int   c2 = __ldg(&ecol[ei + 2]), c3 = __ldg(&ecol[ei + 3]);
        float v0 = __ldg(&eval[ei]),     v1 = __ldg(&eval[ei + 1]);
        float v2 = __ldg(&eval[ei + 2]), v3 = __ldg(&eval[ei + 3]);
        uint2 p0 = __ldg(&H[(size_t)c0 * 32 + lane]);
        uint2 p1 = __ldg(&H[(size_t)c1 * 32 + lane]);
        uint2 p2 = __ldg(&H[(size_t)c2 * 32 + lane]);
        uint2 p3 = __ldg(&H[(size_t)c3 * 32 + lane]);
        float2 a0 = __bfloat1622float2(*(__nv_bfloat162*)&p0.x);
        float2 b0 = __bfloat1622float2(*(__nv_bfloat162*)&p0.y);
        acc.x = fmaf(v0, a0.x, acc.x); acc.y = fmaf(v0, a0.y, acc.y);
        acc.z = fmaf(v0, b0.x, acc.z); acc.w = fmaf(v0, b0.y, acc.w);
        float2 a1 = __bfloat1622float2(*(__nv_bfloat162*)&p1.x);
        float2 b1 = __bfloat1622float2(*(__nv_bfloat162*)&p1.y);
        acc.x = fmaf(v1, a1.x, acc.x); acc.y = fmaf(v1, a1.y, acc.y);
        acc.z = fmaf(v1, b1.x, acc.z); acc.w = fmaf(v1, b1.y, acc.w);
        float2 a2 = __bfloat1622float2(*(__nv_bfloat162*)&p2.x);
        float2 b2 = __bfloat1622float2(*(__nv_bfloat162*)&p2.y);
        acc.x = fmaf(v2, a2.x, acc.x); acc.y = fmaf(v2, a2.y, acc.y);
        acc.z = fmaf(v2, b2.x, acc.z); acc.w = fmaf(v2, b2.y, acc.w);
        float2 a3 = __bfloat1622float2(*(__nv_bfloat162*)&p3.x);
        float2 b3 = __bfloat1622float2(*(__nv_bfloat162*)&p3.y);
        acc.x = fmaf(v3, a3.x, acc.x); acc.y = fmaf(v3, a3.y, acc.y);
        acc.z = fmaf(v3, b3.x, acc.z); acc.w = fmaf(v3, b3.y, acc.w);
    }
    for (; ei < e; ei++) {
        int c   = __ldg(&ecol[ei]);
        float v = __ldg(&eval[ei]);
        uint2 p = __ldg(&H[(size_t)c * 32 + lane]);
        float2 f0 = __bfloat1622float2(*(__nv_bfloat162*)&p.x);
        float2 f1 = __bfloat1622float2(*(__nv_bfloat162*)&p.y);
        acc.x = fmaf(v, f0.x, acc.x); acc.y = fmaf(v, f0.y, acc.y);
        acc.z = fmaf(v, f1.x, acc.z); acc.w = fmaf(v, f1.y, acc.w);
    }
    __nv_bfloat162 o0 = __floats2bfloat162_rn(fmaxf(acc.x, 0.f), fmaxf(acc.y, 0.f));
    __nv_bfloat162 o1 = __floats2bfloat162_rn(fmaxf(acc.z, 0.f), fmaxf(acc.w, 0.f));
    uint2 o; o.x = *(uint32_t*)&o0; o.y = *(uint32_t*)&o1;
    ((uint2*)Hout)[(size_t)gw * 32 + lane] = o;
}

__global__ void spmm_lsm64_kernel(const int* __restrict__ ecol,
                                  const float* __restrict__ eval,
                                  const int* __restrict__ rowptr,
                                  const __nv_bfloat16* __restrict__ Hin,
                                  float* __restrict__ out, int n) {
    int gw = (blockIdx.x * blockDim.x + threadIdx.x) >> 5;
    int lane = threadIdx.x & 31;
    if (gw >= n) return;
    int s = rowptr[gw], e = rowptr[gw + 1];
    const uint32_t* H = (const uint32_t*)Hin;  // row = 32 x (2 bf16)
    float2 acc = make_float2(0.f, 0.f);
    int ei = s;
    for (; ei + 4 <= e; ei += 4) {
        int   c0 = __ldg(&ecol[ei]),     c1 = __ldg(&ecol[ei + 1]);
        int   c2 = __ldg(&ecol[ei + 2]), c3 = __ldg(&ecol[ei + 3]);
        float v0 = __ldg(&eval[ei]),     v1 = __ldg(&eval[ei + 1]);
        float v2 = __ldg(&eval[ei + 2]), v3 = __ldg(&eval[ei + 3]);
        uint32_t p0 = __ldg(&H[(size_t)c0 * 32 + lane]);
        uint32_t p1 = __ldg(&H[(size_t)c1 * 32 + lane]);
        uint32_t p2 = __ldg(&H[(size_t)c2 * 32 + lane]);
        uint32_t p3 = __ldg(&H[(size_t)c3 * 32 + lane]);
        float2 f0 = __bfloat1622float2(*(__nv_bfloat162*)&p0);
        float2 f1 = __bfloat1622float2(*(__nv_bfloat162*)&p1);
        float2 f2 = __bfloat1622float2(*(__nv_bfloat162*)&p2);
        float2 f3 = __bfloat1622float2(*(__nv_bfloat162*)&p3);
        acc.x = fmaf(v0, f0.x, acc.x); acc.y = fmaf(v0, f0.y, acc.y);
        acc.x = fmaf(v1, f1.x, acc.x); acc.y = fmaf(v1, f1.y, acc.y);
        acc.x = fmaf(v2, f2.x, acc.x); acc.y = fmaf(v2, f2.y, acc.y);
        acc.x = fmaf(v3, f3.x, acc.x); acc.y = fmaf(v3, f3.y, acc.y);
    }
    for (; ei < e; ei++) {
        int c   = __ldg(&ecol[ei]);
        float v = __ldg(&eval[ei]);
        uint32_t p = __ldg(&H[(size_t)c * 32 + lane]);
        float2 f = __bfloat1622float2(*(__nv_bfloat162*)&p);
        acc.x = fmaf(v, f.x, acc.x); acc.y = fmaf(v, f.y, acc.y);
    }
    float mx = fmaxf(acc.x, acc.y);
    #pragma unroll
    for (int o = 16; o > 0; o >>= 1) mx = fmaxf(mx, __shfl_xor_sync(0xffffffffu, mx, o));
    float sum = expf(acc.x - mx) + expf(acc.y - mx);
    #pragma unroll
    for (int o = 16; o > 0; o >>= 1) sum += __shfl_xor_sync(0xffffffffu, sum, o);
    float lse = mx + logf(sum);
    ((float2*)out)[(size_t)gw * 32 + lane] = make_float2(acc.x - lse, acc.y - lse);
}

// ============================ launch ============================
extern "C" void kernel_launch(void* const* d_in, const int* in_sizes, int n_in,
                              void* d_out, int out_size) {
    const float* x    = (const float*)d_in[0];
    const void*  erow = d_in[1];
    const void*  ecol = d_in[2];
    const float* W0   = (const float*)d_in[3];
    const float* b0   = (const float*)d_in[4];
    const float* W1   = (const float*)d_in[5];
    const float* b1   = (const float*)d_in[6];
    float* out = (float*)d_out;

    const int n = in_sizes[0] / FEAT0;   // 100000
    const int m = in_sizes[1];           // 1600000

    int*   erow32; cudaGetSymbolAddress((void**)&erow32, g_erow32);
    int*   ecol32; cudaGetSymbolAddress((void**)&ecol32, g_ecol32);
    float* evalp;  cudaGetSymbolAddress((void**)&evalp,  g_eval);
    int*   rowptr; cudaGetSymbolAddress((void**)&rowptr, g_rowptr);
    float* dinv;   cudaGetSymbolAddress((void**)&dinv,   g_dinv);
    __nv_bfloat16 *h0b, *s1b, *h1b, *w0t, *w1t;
    cudaGetSymbolAddress((void**)&h0b, g_h0b);
    cudaGetSymbolAddress((void**)&s1b, g_s1b);
    cudaGetSymbolAddress((void**)&h1b, g_h1b);
    cudaGetSymbolAddress((void**)&w0t, g_w0t);
    cudaGetSymbolAddress((void**)&w1t, g_w1t);

    const int smemG1 = (128 + FEAT0) * 136 * 2;  // 69,632 B
    const int smemG2 = (128 + FEAT1) * 136 * 2;  // 52,224 B
    cudaFuncSetAttribute((const void*)gemm_mma_kernel<FEAT0, float>,
                         cudaFuncAttributeMaxDynamicSharedMemorySize, smemG1);
    cudaFuncSetAttribute((const void*)gemm_mma_kernel<FEAT1, __nv_bfloat16>,
                         cudaFuncAttributeMaxDynamicSharedMemorySize, smemG2);

    const int ntiles = (n + 127) / 128;
    const int nw = n + FEAT0 * FEAT0 + FEAT0 * FEAT1;  // dinv + both weight transposes

    // prep (4 launches)
    detect_kernel<<<1, 256>>>((const unsigned int*)erow, m);
    convert_rowptr_kernel<<<(m + 255) / 256, 256>>>(erow, ecol, m, n, erow32, ecol32, rowptr);
    dinv_weights_kernel<<<(nw + 255) / 256, 256>>>(rowptr, dinv, n, W0, W1, w0t, w1t);
    eval_kernel<<<(m + 255) / 256, 256>>>(erow32, ecol32, dinv, evalp, m);

    // layer 0  (launch #5 = gemm1, #6 = spmm1 -> ncu -s 5 profiles spmm1)
    gemm_mma_kernel<FEAT0, float><<<ntiles, 256, smemG1>>>(x, w0t, b0, h0b, n);
    spmm_relu128_kernel<<<(n + 7) / 8, 256>>>(ecol32, evalp, rowptr, h0b, s1b, n);
    // layer 1
    gemm_mma_kernel<FEAT1, __nv_bfloat16><<<ntiles, 256, smemG2>>>(s1b, w1t, b1, h1b, n);
    spmm_lsm64_kernel<<<(n + 7) / 8, 256>>>(ecol32, evalp, rowptr, h1b, out, n);
}

// round 7
// speedup vs baseline: 2.7319x; 1.1032x over previous
#include <cuda_runtime.h>
#include <cuda_bf16.h>
#include <math.h>
#include <stdint.h>

#define N_NODES_MAX 100000
#define N_EDGES_MAX 1600000
#define FEAT0 128
#define FEAT1 64

// ---------------- scratch (allocation-free: __device__ globals) ----------------
__device__ int            g_is64;
__device__ int            g_ecol32[N_EDGES_MAX];
__device__ int            g_rowptr[N_NODES_MAX + 1];
__device__ float          g_dinv[N_NODES_MAX];
__device__ __nv_bfloat16  g_h0b[(size_t)N_NODES_MAX * FEAT0];  // dinv*(x@W0+b0)
__device__ __nv_bfloat16  g_s1b[(size_t)N_NODES_MAX * FEAT0];  // relu(dinv*spmm)
__device__ __nv_bfloat16  g_h1b[(size_t)N_NODES_MAX * FEAT1];  // dinv*(s1@W1+b1)
__device__ __nv_bfloat16  g_w0t[FEAT0 * FEAT0];   // W0^T [N=128][K=128] bf16
__device__ __nv_bfloat16  g_w1t[FEAT1 * FEAT0];   // W1^T [N=64][K=128]  bf16

// ============================ prep kernels ============================
// dtype detect on the LAST 1024 words of sorted edge_row (int64 -> odd words are 0 high halves).
__global__ void detect_kernel(const unsigned int* __restrict__ raw, int m) {
    __shared__ unsigned int s_nz;
    if (threadIdx.x == 0) s_nz = 0u;
    __syncthreads();
    unsigned int acc = 0u;
    int start = m - 1024;
    for (int w = start + (int)threadIdx.x; w < m; w += (int)blockDim.x)
        if (w & 1) acc |= raw[w];
    if (acc) atomicOr(&s_nz, 1u);
    __syncthreads();
    if (threadIdx.x == 0) g_is64 = (s_nz == 0u) ? 1 : 0;
}

__device__ __forceinline__ int load_edge(const void* p, int i, int is64) {
    return is64 ? (int)((const long long*)p)[i] : ((const int*)p)[i];
}

// convert ecol -> int32 AND build rowptr from sorted erow by boundary detection.
__global__ void convert_rowptr_kernel(const void* __restrict__ erow,
                                      const void* __restrict__ ecol,
                                      int m, int n,
                                      int* __restrict__ ecol32,
                                      int* __restrict__ rowptr) {
    int i = blockIdx.x * blockDim.x + threadIdx.x;
    if (i >= m) return;
    const int is64 = g_is64;
    int cur  = load_edge(erow, i, is64);
    int prev = (i > 0) ? load_edge(erow, i - 1, is64) : -1;
    ecol32[i] = load_edge(ecol, i, is64);
    for (int r = prev + 1; r <= cur; r++) rowptr[r] = i;
    if (i == m - 1)
        for (int r = cur + 1; r <= n; r++) rowptr[r] = m;
}

// dinv for n nodes + both weight transposes (bf16), one launch
__global__ void dinv_weights_kernel(const int* __restrict__ rowptr, float* __restrict__ dinv,
                                    int n, const float* __restrict__ W0,
                                    const float* __restrict__ W1,
                                    __nv_bfloat16* __restrict__ w0t,
                                    __nv_bfloat16* __restrict__ w1t) {
    int i = blockIdx.x * blockDim.x + threadIdx.x;
    if (i < n) {
        int d = rowptr[i + 1] - rowptr[i];
        dinv[i] = (d > 0) ? rsqrtf((float)d) : 0.0f;
        return;
    }
    int j = i - n;
    if (j < FEAT0 * FEAT0) {
        int k = j / FEAT0, c = j % FEAT0;
        w0t[c * FEAT0 + k] = __float2bfloat16(W0[j]);
    } else if (j < FEAT0 * FEAT0 + FEAT0 * FEAT1) {
        int q = j - FEAT0 * FEAT0;
        int k = q / FEAT1, c = q % FEAT1;
        w1t[c * FEAT0 + k] = __float2bfloat16(W1[q]);
    }
}

// ============================ HMMA (mma.sync) bf16 GEMM ============================
__device__ __forceinline__ void mma_bf16(float* d, const uint32_t* a, uint32_t b0, uint32_t b1) {
    asm volatile(
        "mma.sync.aligned.m16n8k16.row.col.f32.bf16.bf16.f32 "
        "{%0,%1,%2,%3}, {%4,%5,%6,%7}, {%8,%9}, {%0,%1,%2,%3};"
        : "+f"(d[0]), "+f"(d[1]), "+f"(d[2]), "+f"(d[3])
        : "r"(a[0]), "r"(a[1]), "r"(a[2]), "r"(a[3]), "r"(b0), "r"(b1));
}

// C[r,:] = dinv[r] * (A[r,:]@Wt^T + bias)   (bf16 out)
template <int N, typename TA>
__global__ void __launch_bounds__(256)
gemm_mma_kernel(const TA* __restrict__ A, const __nv_bfloat16* __restrict__ Wt,
                const float* __restrict__ bias, const float* __restrict__ dinv,
                __nv_bfloat16* __restrict__ C, int nrows) {
    constexpr int K = 128, BM = 128;
    constexpr int SA = 136;
    constexpr int NT = N / 2;
    constexpr int NTILES = NT / 8;

    extern __shared__ __nv_bfloat16 sm[];
    __nv_bfloat16* As = sm;               // [BM][SA]
    __nv_bfloat16* Bs = sm + BM * SA;     // [N][SA]

    const int tid  = threadIdx.x;
    const int wid  = tid >> 5;
    const int lane = tid & 31;
    const int wr   = wid >> 1;
    const int wc   = wid & 1;
    const int gID  = lane >> 2;
    const int tig  = lane & 3;
    const int row0 = blockIdx.x * BM;

    if constexpr (sizeof(TA) == 4) {
        const float4* A4 = (const float4*)A;
        #pragma unroll
        for (int idx = tid; idx < BM * (K / 4); idx += 256) {
            int r = idx >> 5, c4 = idx & 31;
            float4 v = make_float4(0.f, 0.f, 0.f, 0.f);
            if (row0 + r < nrows) v = A4[(size_t)(row0 + r) * 32 + c4];
            __nv_bfloat162 lo = __floats2bfloat162_rn(v.x, v.y);
            __nv_bfloat162 hi = __floats2bfloat162_rn(v.z, v.w);
            uint2 o; o.x = *(uint32_t*)&lo; o.y = *(uint32_t*)&hi;
            *(uint2*)&As[r * SA + c4 * 4] = o;
        }
    } else {
        const uint4* A8 = (const uint4*)A;
        #pragma unroll
        for (int idx = tid; idx < BM * (K / 8); idx += 256) {
            int r = idx >> 4, c8 = idx & 15;
            uint4 v = make_uint4(0, 0, 0, 0);
            if (row0 + r < nrows) v = A8[(size_t)(row0 + r) * 16 + c8];
            *(uint4*)&As[r * SA + c8 * 8] = v;
        }
    }
    {
        const uint4* B8 = (const uint4*)Wt;
        #pragma unroll
        for (int idx = tid; idx < N * (K / 8); idx += 256) {
            int r = idx >> 4, c8 = idx & 15;
            *(uint4*)&Bs[r * SA + c8 * 8] = B8[(size_t)r * 16 + c8];
        }
    }
    __syncthreads();

    float acc[2][NTILES][4];
    #pragma unroll
    for (int mt = 0; mt < 2; mt++)
        #pragma unroll
        for (int nt = 0; nt < NTILES; nt++)
            #pragma unroll
            for (int c = 0; c < 4; c++) acc[mt][nt][c] = 0.f;

    #pragma unroll
    for (int ks = 0; ks < 8; ks++) {
        const int k0 = ks * 16;
        uint32_t a[2][4];
        #pragma unroll
        for (int mt = 0; mt < 2; mt++) {
            const __nv_bfloat16* base = &As[(wr * 32 + mt * 16 + gID) * SA + k0 + 2 * tig];
            a[mt][0] = *(const uint32_t*)(base);
            a[mt][1] = *(const uint32_t*)(base + 8 * SA);
            a[mt][2] = *(const uint32_t*)(base + 8);
            a[mt][3] = *(const uint32_t*)(base + 8 * SA + 8);
        }
        #pragma unroll
        for (int nt = 0; nt < NTILES; nt++) {
            const __nv_bfloat16* bb = &Bs[(wc * NT + nt * 8 + gID) * SA + k0 + 2 * tig];
            uint32_t b0 = *(const uint32_t*)(bb);
            uint32_t b1 = *(const uint32_t*)(bb + 8);
            #pragma unroll
            for (int mt = 0; mt < 2; mt++) mma_bf16(acc[mt][nt], a[mt], b0, b1);
        }
    }

    #pragma unroll
    for (int mt = 0; mt < 2; mt++) {
        const int r_a = row0 + wr * 32 + mt * 16 + gID;
        const float dv0 = (r_a     < nrows) ? __ldg(&dinv[r_a])     : 0.f;
        const float dv1 = (r_a + 8 < nrows) ? __ldg(&dinv[r_a + 8]) : 0.f;
        #pragma unroll
        for (int nt = 0; nt < NTILES; nt++) {
            const int col = wc * NT + nt * 8 + 2 * tig;
            float2 bv = __ldg((const float2*)&bias[col]);
            if (r_a < nrows) {
                __nv_bfloat162 o = __floats2bfloat162_rn(dv0 * (acc[mt][nt][0] + bv.x),
                                                         dv0 * (acc[mt][nt][1] + bv.y));
                *(uint32_t*)&C[(size_t)r_a * N + col] = *(uint32_t*)&o;
            }
            if (r_a + 8 < nrows) {
                __nv_bfloat162 o = __floats2bfloat162_rn(dv1 * (acc[mt][nt][2] + bv.x),
                                                         dv1 * (acc[mt][nt][3] + bv.y));
                *(uint32_t*)&C[(size_t)(r_a + 8) * N + col] = *(uint32_t*)&o;
            }
        }
    }
}

// ============================ SpMM kernels (pure gather, no per-edge values) ============================
// s1[i] = relu(dinv[i] * sum_e H'[col[e]])   (H' already carries dinv[col])
__global__ void spmm_relu128_kernel(const int* __restrict__ ecol,
                                    const int* __restrict__ rowptr,
                                    const float* __restrict__ dinv,
                                    const __nv_bfloat16* __restrict__ Hin,
                                    __nv_bfloat16* __restrict__ Hout, int n) {
    int gw = (blockIdx.x * blockDim.x + threadIdx.x) >> 5;
    int lane = threadIdx.x & 31;
    if (gw >= n) return;
    int s = rowptr[gw], e = rowptr[gw + 1];
    const uint2* H = (const uint2*)Hin;   // row = 32 uint2 (4 bf16/lane)
    float4 acc = make_float4(0.f, 0.f, 0.f, 0.f);
    int ei = s;
    for (; ei + 4 <= e; ei += 4) {
        int c0 = __ldg(&ecol[ei]),     c1 = __ldg(&ecol[ei + 1]);
        int c2 = __ldg(&ecol[ei + 2]), c3 = __ldg(&ecol[ei + 3]);
        uint2 p0 = __ldg(&H[(size_t)c0 * 32 + lane]);
        uint2 p1 = __ldg(&H[(size_t)c1 * 32 + lane]);
        uint2 p2 = __ldg(&H[(size_t)c2 * 32 + lane]);
        uint2 p3 = __ldg(&H[(size_t)c3 * 32 + lane]);
        float2 a0 = __bfloat1622float2(*(__nv_bfloat162*)&p0.x);
        float2 b0 = __bfloat1622float2(*(__nv_bfloat162*)&p0.y);
        acc.x += a0.x; acc.y += a0.y; acc.z += b0.x; acc.w += b0.y;
        float2 a1 = __bfloat1622float2(*(__nv_bfloat162*)&p1.x);
        float2 b1 = __bfloat1622float2(*(__nv_bfloat162*)&p1.y);
        acc.x += a1.x; acc.y += a1.y; acc.z += b1.x; acc.w += b1.y;
        float2 a2 = __bfloat1622float2(*(__nv_bfloat162*)&p2.x);
        float2 b2 = __bfloat1622float2(*(__nv_bfloat162*)&p2.y);
        acc.x += a2.x; acc.y += a2.y; acc.z += b2.x; acc.w += b2.y;
        float2 a3 = __bfloat1622float2(*(__nv_bfloat162*)&p3.x);
        float2 b3 = __bfloat1622float2(*(__nv_bfloat162*)&p3.y);
        acc.x += a3.x; acc.y += a3.y; acc.z += b3.x; acc.w += b3.y;
    }
    for (; ei < e; ei++) {
        int c = __ldg(&ecol[ei]);
        uint2 p = __ldg(&H[(size_t)c * 32 + lane]);
        float2 f0 = __bfloat1622float2(*(__nv_bfloat162*)&p.x);
        float2 f1 = __bfloat1622float2(*(__nv_bfloat162*)&p.y);
        acc.x += f0.x; acc.y += f0.y; acc.z += f1.x; acc.w += f1.y;
    }
    float di = __ldg(&dinv[gw]);
    __nv_bfloat162 o0 = __floats2bfloat162_rn(fmaxf(di * acc.x, 0.f), fmaxf(di * acc.y, 0.f));
    __nv_bfloat162 o1 = __floats2bfloat162_rn(fmaxf(di * acc.z, 0.f), fmaxf(di * acc.w, 0.f));
    uint2 o; o.x = *(uint32_t*)&o0; o.y = *(uint32_t*)&o1;
    ((uint2*)Hout)[(size_t)gw * 32 + lane] = o;
}

// out = log_softmax(dinv[row] * sum_e H'[col[e]])
__global__ void spmm_lsm64_kernel(const int* __restrict__ ecol,
                                  const int* __restrict__ rowptr,
                                  const float* __restrict__ dinv,
                                  const __nv_bfloat16* __restrict__ Hin,
                                  float* __restrict__ out, int n) {
    int gw = (blockIdx.x * blockDim.x + threadIdx.x) >> 5;
    int lane = threadIdx.x & 31;
    if (gw >= n) return;
    int s = rowptr[gw], e = rowptr[gw + 1];
    const uint32_t* H = (const uint32_t*)Hin;  // row = 32 x (2 bf16)
    float2 acc = make_float2(0.f, 0.f);
    int ei = s;
    for (; ei + 4 <= e; ei += 4) {
        int c0 = __ldg(&ecol[ei]),     c1 = __ldg(&ecol[ei + 1]);
        int c2 = __ldg(&ecol[ei + 2]), c3 = __ldg(&ecol[ei + 3]);
        uint32_t p0 = __ldg(&H[(size_t)c0 * 32 + lane]);
        uint32_t p1 = __ldg(&H[(size_t)c1 * 32 + lane]);
        uint32_t p2 = __ldg(&H[(size_t)c2 * 32 + lane]);
        uint32_t p3 = __ldg(&H[(size_t)c3 * 32 + lane]);
        float2 f0 = __bfloat1622float2(*(__nv_bfloat162*)&p0);
        float2 f1 = __bfloat1622float2(*(__nv_bfloat162*)&p1);
        float2 f2 = __bfloat1622float2(*(__nv_bfloat162*)&p2);
        float2 f3 = __bfloat1622float2(*(__nv_bfloat162*)&p3);
        acc.x += f0.x + f1.x + f2.x + f3.x;
        acc.y += f0.y + f1.y + f2.y + f3.y;
    }
    for (; ei < e; ei++) {
        int c = __ldg(&ecol[ei]);
        uint32_t p = __ldg(&H[(size_t)c * 32 + lane]);
        float2 f = __bfloat1622float2(*(__nv_bfloat162*)&p);
        acc.x += f.x; acc.y += f.y;
    }
    float di = __ldg(&dinv[gw]);
    acc.x *= di; acc.y *= di;
    float mx = fmaxf(acc.x, acc.y);
    #pragma unroll
    for (int o = 16; o > 0; o >>= 1) mx = fmaxf(mx, __shfl_xor_sync(0xffffffffu, mx, o));
    float sum = expf(acc.x - mx) + expf(acc.y - mx);
    #pragma unroll
    for (int o = 16; o > 0; o >>= 1) sum += __shfl_xor_sync(0xffffffffu, sum, o);
    float lse = mx + logf(sum);
    ((float2*)out)[(size_t)gw * 32 + lane] = make_float2(acc.x - lse, acc.y - lse);
}

// ============================ launch ============================
extern "C" void kernel_launch(void* const* d_in, const int* in_sizes, int n_in,
                              void* d_out, int out_size) {
    const float* x    = (const float*)d_in[0];
    const void*  erow = d_in[1];
    const void*  ecol = d_in[2];
    const float* W0   = (const float*)d_in[3];
    const float* b0   = (const float*)d_in[4];
    const float* W1   = (const float*)d_in[5];
    const float* b1   = (const float*)d_in[6];
    float* out = (float*)d_out;

    const int n = in_sizes[0] / FEAT0;   // 100000
    const int m = in_sizes[1];           // 1600000

    int*   ecol32; cudaGetSymbolAddress((void**)&ecol32, g_ecol32);
    int*   rowptr; cudaGetSymbolAddress((void**)&rowptr, g_rowptr);
    float* dinv;   cudaGetSymbolAddress((void**)&dinv,   g_dinv);
    __nv_bfloat16 *h0b, *s1b, *h1b, *w0t, *w1t;
    cudaGetSymbolAddress((void**)&h0b, g_h0b);
    cudaGetSymbolAddress((void**)&s1b, g_s1b);
    cudaGetSymbolAddress((void**)&h1b, g_h1b);
    cudaGetSymbolAddress((void**)&w0t, g_w0t);
    cudaGetSymbolAddress((void**)&w1t, g_w1t);

    const int smemG1 = (128 + FEAT0) * 136 * 2;  // 69,632 B
    const int smemG2 = (128 + FEAT1) * 136 * 2;  // 52,224 B
    cudaFuncSetAttribute((const void*)gemm_mma_kernel<FEAT0, float>,
                         cudaFuncAttributeMaxDynamicSharedMemorySize, smemG1);
    cudaFuncSetAttribute((const void*)gemm_mma_kernel<FEAT1, __nv_bfloat16>,
                         cudaFuncAttributeMaxDynamicSharedMemorySize, smemG2);

    const int ntiles = (n + 127) / 128;
    const int nw = n + FEAT0 * FEAT0 + FEAT0 * FEAT1;

    // prep (3 launches)
    detect_kernel<<<1, 256>>>((const unsigned int*)erow, m);
    convert_rowptr_kernel<<<(m + 255) / 256, 256>>>(erow, ecol, m, n, ecol32, rowptr);
    dinv_weights_kernel<<<(nw + 255) / 256, 256>>>(rowptr, dinv, n, W0, W1, w0t, w1t);

    // layer 0
    gemm_mma_kernel<FEAT0, float><<<ntiles, 256, smemG1>>>(x, w0t, b0, dinv, h0b, n);
    spmm_relu128_kernel<<<(n + 7) / 8, 256>>>(ecol32, rowptr, dinv, h0b, s1b, n);
    // layer 1
    gemm_mma_kernel<FEAT1, __nv_bfloat16><<<ntiles, 256, smemG2>>>(s1b, w1t, b1, dinv, h1b, n);
    spmm_lsm64_kernel<<<(n + 7) / 8, 256>>>(ecol32, rowptr, dinv, h1b, out, n);
}